// round 1
// baseline (speedup 1.0000x reference)
#include <cuda_runtime.h>
#include <math.h>

#define BB 2
#define TT 2048
#define SS 2048
#define DM 1024
#define NH 16
#define DH 64
#define KK 1024

// Scratch (static device globals — allocation-free rule)
__device__ float g_qn[(size_t)BB*NH*TT*DH];    // normalized+scaled Q, head layout
__device__ float g_kn[(size_t)BB*NH*SS*DH];    // normalized K, head layout
__device__ float g_vh[(size_t)BB*NH*SS*DH];    // projected V, head layout
__device__ float g_vals[(size_t)BB*TT*DM];     // attention output, [B,T,D]
__device__ float g_biasT[(size_t)NH*TT*SS];    // bias transposed to [H,T,S]

// ---------------------------------------------------------------------------
// Bias transpose: [T,S,H] -> [H,T,S]. Tile: 4 t x 64 s x 16 h. Coalesced both ways.
// ---------------------------------------------------------------------------
__global__ __launch_bounds__(256) void bias_transpose_kernel(const float* __restrict__ in) {
    __shared__ float sm[16 * 261];
    const int t0 = blockIdx.x * 4;
    const int s0 = blockIdx.y * 64;
    const int tid = threadIdx.x;
#pragma unroll
    for (int tt = 0; tt < 4; tt++) {
        const float* src = in + ((size_t)(t0 + tt) * SS + s0) * NH;
#pragma unroll
        for (int p = 0; p < 4; p++) {
            int idx = p * 256 + tid;       // 0..1023 over (ss, h)
            int h = idx & 15, ss = idx >> 4;
            sm[h * 261 + tt * 64 + ss] = src[idx];
        }
    }
    __syncthreads();
#pragma unroll
    for (int p = 0; p < 16; p++) {
        int idx = p * 256 + tid;           // 0..4095
        int ss = idx & 63;
        int combo = idx >> 6;              // (h, tt)
        int tt = combo & 3, h = combo >> 2;
        g_biasT[(size_t)h * TT * SS + (size_t)(t0 + tt) * SS + s0 + ss] =
            sm[h * 261 + tt * 64 + ss];
    }
}

// ---------------------------------------------------------------------------
// GEMM C = A[4096,1024] * W[1024,1024]^T   (NT: both K-contiguous)
// 64x64 tile, BK=16, 256 threads, 4x4 microtile.
// MODE 0: plain output (A = g_vals, C = d_out)
// MODE 1: head-layout output -> g_vh (V projection, no norm)
// MODE 2: head-layout + L2 row norm -> g_kn (K)
// MODE 3: head-layout + L2 norm + per-head logit scale -> g_qn (Q)
// ---------------------------------------------------------------------------
template <int MODE>
__global__ __launch_bounds__(256) void gemm_nt_kernel(const float* __restrict__ A,
                                                      const float* __restrict__ W,
                                                      float* __restrict__ Cplain,
                                                      const float* __restrict__ ls) {
    __shared__ float As[16][65];
    __shared__ float Ws[16][65];
    const int m0 = blockIdx.x * 64;
    const int n0 = blockIdx.y * 64;
    const int tid = threadIdx.x;
    const int tx = tid & 15, ty = tid >> 4;

    const float* Ar = (MODE == 0) ? (const float*)g_vals : A;

    float acc[4][4] = {};
    for (int k0 = 0; k0 < KK; k0 += 16) {
        int kk = tid & 15;
        int rbase = tid >> 4;
#pragma unroll
        for (int p = 0; p < 4; p++) {
            int r = p * 16 + rbase;
            As[kk][r] = Ar[(size_t)(m0 + r) * KK + k0 + kk];
            Ws[kk][r] = W[(size_t)(n0 + r) * KK + k0 + kk];
        }
        __syncthreads();
#pragma unroll
        for (int k = 0; k < 16; k++) {
            float a[4], b[4];
#pragma unroll
            for (int i = 0; i < 4; i++) a[i] = As[k][ty * 4 + i];
#pragma unroll
            for (int j = 0; j < 4; j++) b[j] = Ws[k][tx * 4 + j];
#pragma unroll
            for (int i = 0; i < 4; i++)
#pragma unroll
                for (int j = 0; j < 4; j++) acc[i][j] += a[i] * b[j];
        }
        __syncthreads();
    }

    if (MODE >= 2) {
        // L2-normalize each row over the 64 cols of this tile (== one head width)
        float inv[4];
#pragma unroll
        for (int i = 0; i < 4; i++) {
            float ssq = 0.f;
#pragma unroll
            for (int j = 0; j < 4; j++) ssq += acc[i][j] * acc[i][j];
#pragma unroll
            for (int msk = 8; msk; msk >>= 1)
                ssq += __shfl_xor_sync(0xffffffffu, ssq, msk, 16);
            inv[i] = 1.0f / fmaxf(sqrtf(ssq), 1e-12f);
        }
        float hscale = 1.0f;
        if (MODE == 3) {
            int h = n0 >> 6;
            hscale = expf(fminf(ls[h], 4.6051701859880914f)); // log(100)
        }
#pragma unroll
        for (int i = 0; i < 4; i++)
#pragma unroll
            for (int j = 0; j < 4; j++) acc[i][j] *= inv[i] * hscale;
    }

    float* Cp;
    if (MODE == 0) Cp = Cplain;
    else if (MODE == 1) Cp = g_vh;
    else if (MODE == 2) Cp = g_kn;
    else Cp = g_qn;

#pragma unroll
    for (int i = 0; i < 4; i++) {
        int m = m0 + ty * 4 + i;
#pragma unroll
        for (int j = 0; j < 4; j++) {
            int n = n0 + tx * 4 + j;
            if (MODE == 0) {
                Cp[(size_t)m * DM + n] = acc[i][j];
            } else {
                int b = m >> 11, t = m & 2047;
                int h = n >> 6, dh = n & 63;
                Cp[(((size_t)(b * NH + h)) * TT + t) * DH + dh] = acc[i][j];
            }
        }
    }
}

// ---------------------------------------------------------------------------
// Flash attention: per (b, h, 64-row q tile). Online softmax, fp32.
// Dynamic smem: Qs/Ks/Vs/Ps each 64x65 floats.
// ---------------------------------------------------------------------------
#define ATT_SMEM (4 * 64 * 65 * (int)sizeof(float))

__global__ __launch_bounds__(256) void attention_kernel() {
    extern __shared__ float sm[];
    float* Qs = sm;                 // [64][65]
    float* Ks = sm + 64 * 65;       // [64][65]
    float* Vs = sm + 2 * 64 * 65;   // [64][65]
    float* Ps = sm + 3 * 64 * 65;   // [64][65]

    const int t0 = blockIdx.x * 64;
    const int h = blockIdx.y;
    const int b = blockIdx.z;
    const int tid = threadIdx.x;
    const int tx = tid & 15, ty = tid >> 4;

    const float* qptr = g_qn + (((size_t)(b * NH + h)) * TT + t0) * DH;
    const float* kbase = g_kn + ((size_t)(b * NH + h)) * SS * DH;
    const float* vbase = g_vh + ((size_t)(b * NH + h)) * SS * DH;
    const float* bptr = g_biasT + (size_t)h * TT * SS + (size_t)t0 * SS;

    // Load Q tile once
#pragma unroll
    for (int p = 0; p < 16; p++) {
        int idx = p * 256 + tid;
        int r = idx >> 6, c = idx & 63;
        Qs[r * 65 + c] = qptr[(size_t)r * DH + c];
    }

    float m_prev[4], lsum[4], o[4][4];
#pragma unroll
    for (int i = 0; i < 4; i++) {
        m_prev[i] = -1e30f;
        lsum[i] = 0.f;
#pragma unroll
        for (int j = 0; j < 4; j++) o[i][j] = 0.f;
    }

    for (int s0 = 0; s0 < SS; s0 += 64) {
        __syncthreads();  // protect Ks/Vs/Ps from previous iteration reads
#pragma unroll
        for (int p = 0; p < 16; p++) {
            int idx = p * 256 + tid;
            int r = idx >> 6, c = idx & 63;
            Ks[r * 65 + c] = kbase[(size_t)(s0 + r) * DH + c];
            Vs[r * 65 + c] = vbase[(size_t)(s0 + r) * DH + c];
        }
        __syncthreads();

        // scores = Q * K^T
        float sc[4][4] = {};
#pragma unroll
        for (int k = 0; k < 64; k++) {
            float a[4], bv[4];
#pragma unroll
            for (int i = 0; i < 4; i++) a[i] = Qs[(ty * 4 + i) * 65 + k];
#pragma unroll
            for (int j = 0; j < 4; j++) bv[j] = Ks[(tx * 4 + j) * 65 + k];
#pragma unroll
            for (int i = 0; i < 4; i++)
#pragma unroll
                for (int j = 0; j < 4; j++) sc[i][j] += a[i] * bv[j];
        }
        // + bias (coalesced from transposed buffer)
#pragma unroll
        for (int i = 0; i < 4; i++) {
            const float* bp = bptr + (size_t)(ty * 4 + i) * SS + s0 + tx * 4;
#pragma unroll
            for (int j = 0; j < 4; j++) sc[i][j] += bp[j];
        }

        // online softmax (row reductions across the 16-lane tx group)
#pragma unroll
        for (int i = 0; i < 4; i++) {
            float mx = fmaxf(fmaxf(sc[i][0], sc[i][1]), fmaxf(sc[i][2], sc[i][3]));
#pragma unroll
            for (int msk = 8; msk; msk >>= 1)
                mx = fmaxf(mx, __shfl_xor_sync(0xffffffffu, mx, msk, 16));
            float m_new = fmaxf(m_prev[i], mx);
            float rs = 0.f;
#pragma unroll
            for (int j = 0; j < 4; j++) {
                sc[i][j] = __expf(sc[i][j] - m_new);
                rs += sc[i][j];
            }
#pragma unroll
            for (int msk = 8; msk; msk >>= 1)
                rs += __shfl_xor_sync(0xffffffffu, rs, msk, 16);
            float alpha = __expf(m_prev[i] - m_new);
            lsum[i] = lsum[i] * alpha + rs;
            m_prev[i] = m_new;
#pragma unroll
            for (int j = 0; j < 4; j++) o[i][j] *= alpha;
        }

        // stage P and do o += P * V
#pragma unroll
        for (int i = 0; i < 4; i++)
#pragma unroll
            for (int j = 0; j < 4; j++) Ps[(ty * 4 + i) * 65 + tx * 4 + j] = sc[i][j];
        __syncthreads();
#pragma unroll
        for (int k = 0; k < 64; k++) {
            float a[4], bv[4];
#pragma unroll
            for (int i = 0; i < 4; i++) a[i] = Ps[(ty * 4 + i) * 65 + k];
#pragma unroll
            for (int j = 0; j < 4; j++) bv[j] = Vs[k * 65 + tx * 4 + j];
#pragma unroll
            for (int i = 0; i < 4; i++)
#pragma unroll
                for (int j = 0; j < 4; j++) o[i][j] += a[i] * bv[j];
        }
    }

    // epilogue: divide by l, write to [B,T,D] for the output GEMM
#pragma unroll
    for (int i = 0; i < 4; i++) {
        float inv = 1.0f / lsum[i];
        int t = t0 + ty * 4 + i;
        float* dst = g_vals + ((size_t)(b * TT + t)) * DM + h * DH + tx * 4;
#pragma unroll
        for (int j = 0; j < 4; j++) dst[j] = o[i][j] * inv;
    }
}

// ---------------------------------------------------------------------------
extern "C" void kernel_launch(void* const* d_in, const int* in_sizes, int n_in,
                              void* d_out, int out_size) {
    const float* q    = (const float*)d_in[0];
    const float* k    = (const float*)d_in[1];
    const float* v    = (const float*)d_in[2];
    const float* bias = (const float*)d_in[3];
    const float* Wqkv = (const float*)d_in[4];
    const float* Wout = (const float*)d_in[5];
    const float* ls   = (const float*)d_in[6];
    float* out = (float*)d_out;

    cudaFuncSetAttribute(attention_kernel,
                         cudaFuncAttributeMaxDynamicSharedMemorySize, ATT_SMEM);

    bias_transpose_kernel<<<dim3(TT / 4, SS / 64), 256>>>(bias);

    dim3 ggrid(4096 / 64, DM / 64);
    gemm_nt_kernel<3><<<ggrid, 256>>>(q, Wqkv, nullptr, ls);       // Q: norm+scale
    gemm_nt_kernel<2><<<ggrid, 256>>>(k, Wqkv, nullptr, nullptr);  // K: norm
    gemm_nt_kernel<1><<<ggrid, 256>>>(v, Wqkv, nullptr, nullptr);  // V

    attention_kernel<<<dim3(TT / 64, NH, BB), 256, ATT_SMEM>>>();

    gemm_nt_kernel<0><<<ggrid, 256>>>(nullptr, Wout, out, nullptr); // output proj
}